// round 11
// baseline (speedup 1.0000x reference)
#include <cuda_runtime.h>
#include <cuda_bf16.h>
#include <stdint.h>

// ---------------------------------------------------------------------------
// GLCM layer, one kernel, 4-way angle split:
//   out[b, a*64+code, py, px] =
//     (1/1024) * sum_{t in 36x36 ext. window} wy(i)*wx(j) *
//                [ code(reflect(t)) == code ]
// where code(s) = 8*gl(s) + gl(clamp(s + shift_a)), gl = ceil(x/32)-1.
//
// Each CTA handles one (batch, pool-cell, angle-pair). Angle pairs own
// disjoint output channels -> no cross-CTA reduction. Grid 512 x 512thr
// gives 4 co-resident CTAs/SM (2048 thr, regs 32 -> exactly fits), so
// barrier stalls in one CTA are hidden by the other three.
// Tile is gathered with CLAMPED image coords so neighbor reads need no
// clamp: all shifted indices provably lie in [0,38).
// ---------------------------------------------------------------------------

#define H 256
#define W 256
#define NPIX (H * W)
#define NB 2
#define L2BINS 64
#define POOL 32
#define EXT 36          // 32 + 2*2 (box radius)
#define TILE 38         // 36 + 1-px shift halo (image coords [P0-3, P0+34])
#define TSTRIDE 40
#define NT 512
#define NW 16           // warps = per-warp histograms
#define NA 2            // angles per CTA
#define NBINS (NA * L2BINS)   // 128

// neighbor offsets inside the padded tile for angles 0..7
// shifts: (1,0) (1,-1) (0,-1) (-1,-1) (-1,0) (-1,1) (0,1) (1,1)
__device__ __constant__ int c_off[8] = {
    1, -TSTRIDE + 1, -TSTRIDE, -TSTRIDE - 1,
   -1,  TSTRIDE - 1,  TSTRIDE,  TSTRIDE + 1
};

__global__ __launch_bounds__(NT, 4)
void glcm_kernel(const float* __restrict__ x, float* __restrict__ out) {
    const int px = blockIdx.x;            // 0..7
    const int py = blockIdx.y;            // 0..7
    const int b  = blockIdx.z >> 2;       // 0..1
    const int ag = blockIdx.z & 3;        // angle pair: angles {2*ag, 2*ag+1}
    const int X0 = px * POOL;
    const int Y0 = py * POOL;
    const int tid = threadIdx.x;

    __shared__ int8_t tile[TILE * TSTRIDE];
    __shared__ int    hist[NW][NBINS];    // 16 x 128 ints = 8 KB

    // ---- issue all tile LDGs first, then zero hist while they're in flight
    const float* xb = x + b * NPIX;
    float v[3];
    int   rr[3], cc[3];
    #pragma unroll
    for (int k = 0; k < 3; k++) {
        int idx = tid + k * NT;
        rr[k] = idx / TILE; cc[k] = idx % TILE;
        if (idx < TILE * TILE) {
            int gy = min(max(Y0 - 3 + rr[k], 0), H - 1);
            int gx = min(max(X0 - 3 + cc[k], 0), W - 1);
            v[k] = xb[gy * W + gx];
        }
    }

    // zero histograms while LDGs are outstanding (1 int4 store per thread)
    ((int4*)hist)[tid] = make_int4(0, 0, 0, 0);

    // quantize + store tile: gl = ceil(v/32) - 1 == searchsorted_left - 1
    #pragma unroll
    for (int k = 0; k < 3; k++) {
        int idx = tid + k * NT;
        if (idx < TILE * TILE)
            tile[rr[k] * TSTRIDE + cc[k]] =
                (int8_t)(__float2int_ru(v[k] * 0.03125f) - 1);
    }
    __syncthreads();

    int* whist = hist[tid >> 5];
    const int off0 = c_off[2 * ag];
    const int off1 = c_off[2 * ag + 1];

    for (int pos = tid; pos < EXT * EXT; pos += NT) {
        int i = pos / EXT, j = pos % EXT;
        // separable triangular weights 1,2,3,4,5,...,5,4,3,2,1
        int wgt = min(min(i + 1, EXT - i), 5) * min(min(j + 1, EXT - j), 5);

        // reflect-pad mapping for the box-filter position
        int ty = Y0 - 2 + i; if (ty < 0) ty = -ty; else if (ty > H - 1) ty = 2 * (H - 1) - ty;
        int tx = X0 - 2 + j; if (tx < 0) tx = -tx; else if (tx > W - 1) tx = 2 * (W - 1) - tx;

        const int8_t* base = &tile[(ty - Y0 + 3) * TSTRIDE + (tx - X0 + 3)];
        int g1 = base[0];
        int n0 = base[off0];
        int n1 = base[off1];

        int c8 = g1 << 3;
        int code0 = c8 + n0;                 // negative iff x==0 cases (reject)
        int code1 = c8 + n1;
        if ((unsigned)code0 < (unsigned)L2BINS)
            atomicAdd(&whist[code0], wgt);
        if ((unsigned)code1 < (unsigned)L2BINS)
            atomicAdd(&whist[L2BINS + code1], wgt);
    }
    __syncthreads();

    // reduce 16 histograms; write this CTA's disjoint output slice
    const float inv = 1.0f / (float)(POOL * POOL);
    if (tid < NBINS) {
        int s = 0;
        #pragma unroll
        for (int wp = 0; wp < NW; wp++) s += hist[wp][tid];
        int ch = ag * NBINS + tid;           // global channel in [0,512)
        out[((b * 512 + ch) * 8 + py) * 8 + px] = (float)s * inv;
    }
}

extern "C" void kernel_launch(void* const* d_in, const int* in_sizes, int n_in,
                              void* d_out, int out_size) {
    const float* x = (const float*)d_in[0];
    float* out = (float*)d_out;
    dim3 grid(8, 8, NB * 4);
    glcm_kernel<<<grid, NT>>>(x, out);
}

// round 12
// speedup vs baseline: 1.3478x; 1.3478x over previous
#include <cuda_runtime.h>
#include <cuda_bf16.h>
#include <stdint.h>

// ---------------------------------------------------------------------------
// GLCM layer, one kernel, 2-way angle split (R9 shape + instruction diet):
//   out[b, a*64+code, py, px] =
//     (1/1024) * sum_{t in 36x36 ext. window} wy(i)*wx(j) *
//                [ code(reflect(t)) == code ]
// where code(s) = 8*gl(s) + gl(clamp(s + shift_a)), gl = ceil(x/32)-1.
//
// Each CTA: one (batch, pool-cell, angle-group-of-4). Angle groups own
// disjoint output channels -> no cross-CTA reduction. Tile gathered with
// CLAMPED image coords so neighbor reads need no clamp (indices in [0,38)).
// Interior pool cells (36/64) take a reflect-free fast path (CTA-uniform).
// Neighbor offsets are template immediates -> LDS [R+imm], no addr math.
// ---------------------------------------------------------------------------

#define H 256
#define W 256
#define NPIX (H * W)
#define NB 2
#define L2BINS 64
#define POOL 32
#define EXT 36          // 32 + 2*2 (box radius)
#define TILE 38         // 36 + 1-px shift halo (image coords [P0-3, P0+34])
#define TSTRIDE 40
#define NT 512
#define NW 8            // histogram copies (warp pairs share)
#define NBINS 256       // 4 angles x 64 codes per CTA

template<int O0, int O1, int O2, int O3, bool INTERIOR>
__device__ __forceinline__
void hist_loop(const int8_t* __restrict__ tile, int* __restrict__ whist,
               int tid, int Y0, int X0) {
    #pragma unroll
    for (int t = 0; t < 3; t++) {
        int pos = tid + t * NT;
        if (t == 2 && pos >= EXT * EXT) break;
        int i = pos / EXT;
        int j = pos - i * EXT;

        const int8_t* base;
        if (INTERIOR) {
            base = &tile[(i + 1) * TSTRIDE + (j + 1)];
        } else {
            // reflect-pad mapping for the box-filter position
            int ty = Y0 - 2 + i; if (ty < 0) ty = -ty; else if (ty > H - 1) ty = 2 * (H - 1) - ty;
            int tx = X0 - 2 + j; if (tx < 0) tx = -tx; else if (tx > W - 1) tx = 2 * (W - 1) - tx;
            base = &tile[(ty - Y0 + 3) * TSTRIDE + (tx - X0 + 3)];
        }

        // 5 LDS with immediate offsets, issued before the weight math
        int g1 = base[0];
        int n0 = base[O0];
        int n1 = base[O1];
        int n2 = base[O2];
        int n3 = base[O3];

        // separable triangular weights 1,2,3,4,5,...,5,4,3,2,1
        int wgt = min(min(i + 1, EXT - i), 5) * min(min(j + 1, EXT - j), 5);

        int c8 = g1 << 3;
        int c0 = c8 + n0, c1 = c8 + n1, c2 = c8 + n2, c3 = c8 + n3;
        // guard matches reference one-hot: only codes in [0,64) are counted
        if ((unsigned)c0 < (unsigned)L2BINS) atomicAdd(&whist[c0], wgt);
        if ((unsigned)c1 < (unsigned)L2BINS) atomicAdd(&whist[L2BINS + c1], wgt);
        if ((unsigned)c2 < (unsigned)L2BINS) atomicAdd(&whist[2 * L2BINS + c2], wgt);
        if ((unsigned)c3 < (unsigned)L2BINS) atomicAdd(&whist[3 * L2BINS + c3], wgt);
    }
}

__global__ __launch_bounds__(NT, 4)
void glcm_kernel(const float* __restrict__ x, float* __restrict__ out) {
    const int px = blockIdx.x;            // 0..7
    const int py = blockIdx.y;            // 0..7
    const int b  = blockIdx.z >> 1;       // 0..1
    const int ag = blockIdx.z & 1;        // angle group: 0 -> angles 0-3, 1 -> 4-7
    const int X0 = px * POOL;
    const int Y0 = py * POOL;
    const int tid = threadIdx.x;

    __shared__ int8_t tile[TILE * TSTRIDE];
    __shared__ int    hist[NW][NBINS];    // 8 x 256 ints = 8 KB

    // ---- issue all tile LDGs first, zero hist while they're in flight ----
    const float* xb = x + b * NPIX;
    float v[3];
    int   rr[3], cc[3];
    #pragma unroll
    for (int k = 0; k < 3; k++) {
        int idx = tid + k * NT;
        rr[k] = idx / TILE; cc[k] = idx % TILE;
        if (idx < TILE * TILE) {
            int gy = min(max(Y0 - 3 + rr[k], 0), H - 1);
            int gx = min(max(X0 - 3 + cc[k], 0), W - 1);
            v[k] = xb[gy * W + gx];
        }
    }

    // zero histograms: exactly one int4 per thread (8*256/4 = 512)
    ((int4*)hist)[tid] = make_int4(0, 0, 0, 0);

    // quantize + store tile: gl = ceil(v/32) - 1 == searchsorted_left - 1
    #pragma unroll
    for (int k = 0; k < 3; k++) {
        int idx = tid + k * NT;
        if (idx < TILE * TILE)
            tile[rr[k] * TSTRIDE + cc[k]] =
                (int8_t)(__float2int_ru(v[k] * 0.03125f) - 1);
    }
    __syncthreads();

    int* whist = hist[(tid >> 5) & (NW - 1)];   // warp pairs share a copy

    // CTA-uniform dispatch: interior cells never touch reflect/clamp paths
    const bool interior = ((unsigned)(px - 1) < 6u) && ((unsigned)(py - 1) < 6u);
    // shifts: group 0 = (1,0)(1,-1)(0,-1)(-1,-1); group 1 = (-1,0)(-1,1)(0,1)(1,1)
    if (ag == 0) {
        if (interior) hist_loop< 1, -TSTRIDE + 1, -TSTRIDE, -TSTRIDE - 1, true >(tile, whist, tid, Y0, X0);
        else          hist_loop< 1, -TSTRIDE + 1, -TSTRIDE, -TSTRIDE - 1, false>(tile, whist, tid, Y0, X0);
    } else {
        if (interior) hist_loop<-1,  TSTRIDE - 1,  TSTRIDE,  TSTRIDE + 1, true >(tile, whist, tid, Y0, X0);
        else          hist_loop<-1,  TSTRIDE - 1,  TSTRIDE,  TSTRIDE + 1, false>(tile, whist, tid, Y0, X0);
    }
    __syncthreads();

    // reduce 8 histograms; write this CTA's disjoint output slice
    const float inv = 1.0f / (float)(POOL * POOL);
    if (tid < NBINS) {
        int s = 0;
        #pragma unroll
        for (int wp = 0; wp < NW; wp++) s += hist[wp][tid];
        int ch = ag * NBINS + tid;           // global channel in [0,512)
        out[((b * 512 + ch) * 8 + py) * 8 + px] = (float)s * inv;
    }
}

extern "C" void kernel_launch(void* const* d_in, const int* in_sizes, int n_in,
                              void* d_out, int out_size) {
    const float* x = (const float*)d_in[0];
    float* out = (float*)d_out;
    dim3 grid(8, 8, NB * 2);
    glcm_kernel<<<grid, NT>>>(x, out);
}